// round 1
// baseline (speedup 1.0000x reference)
#include <cuda_runtime.h>
#include <cstdint>
#include <cstddef>

// Problem constants
#define B_  2
#define S_  2048
#define H_  2048
#define NH_ 16
#define NKV_ 8
#define HD_ 128
#define BS_ 4096           // B_*S_
#define SCALE_ 0.08838834764831845f  // HD^-0.5

// ---------------- scratch (device globals — no runtime alloc allowed) ----------------
__device__ float g_qraw[(size_t)BS_ * (2 * NH_ * HD_)];       // [bs, 4096]  (query|gate interleaved per head)
__device__ float g_kraw[(size_t)BS_ * (NKV_ * HD_)];          // [bs, 1024]
__device__ float g_vraw[(size_t)BS_ * (NKV_ * HD_)];          // [bs, 1024]
__device__ float g_q  [(size_t)B_ * NH_  * S_ * HD_];         // [b,h,s,d]
__device__ float g_k  [(size_t)B_ * NKV_ * S_ * HD_];         // [b,kvh,s,d]
__device__ float g_vt [(size_t)B_ * NKV_ * HD_ * S_];         // [b,kvh,d,s]  (V transposed)
__device__ float g_avp[(size_t)B_ * NH_  * S_ * HD_];         // [b,h,q,d]  (P@V)
__device__ float g_av [(size_t)BS_ * (NH_ * HD_)];            // [bs, 2048] gated, ready for Wo

// ---------------- generic batched GEMM: C = alpha * A (MxK) * B(NxK)^T ----------------
// A rows contiguous (lda=K), B rows contiguous (ldb=K), C row stride = N.
// gqaB: batch z = b*NH+h maps B operand to kv-head batch (b*NKV + h/2).
__global__ __launch_bounds__(256) void gemm_nt(
    const float* __restrict__ A, const float* __restrict__ Bm, float* __restrict__ C,
    int M, int N, int K,
    long long sA, long long sB, long long sC,
    float alpha, int gqaB)
{
    int z = blockIdx.z;
    long long offB;
    if (gqaB) { int b = z >> 4; int h = z & 15; offB = ((long long)b * NKV_ + (h >> 1)) * sB; }
    else        offB = (long long)z * sB;
    A  += (long long)z * sA;
    Bm += offB;
    C  += (long long)z * sC;

    __shared__ __align__(16) float As[16][68];
    __shared__ __align__(16) float Bs[16][68];

    int tid = threadIdx.x;
    int lr = tid >> 2;            // 0..63
    int lc = (tid & 3) << 2;      // 0,4,8,12
    int tx = tid & 15;
    int ty = tid >> 4;

    int rowA = blockIdx.y * 64 + lr;
    int rowB = blockIdx.x * 64 + lr;

    const float* Aptr = A + (long long)rowA * K + lc;
    const float* Bptr = Bm + (long long)rowB * K + lc;

    float acc[4][4] = {};

    for (int k0 = 0; k0 < K; k0 += 16) {
        float4 a4 = *(const float4*)(Aptr + k0);
        float4 b4 = *(const float4*)(Bptr + k0);
        As[lc+0][lr]=a4.x; As[lc+1][lr]=a4.y; As[lc+2][lr]=a4.z; As[lc+3][lr]=a4.w;
        Bs[lc+0][lr]=b4.x; Bs[lc+1][lr]=b4.y; Bs[lc+2][lr]=b4.z; Bs[lc+3][lr]=b4.w;
        __syncthreads();
        #pragma unroll
        for (int kk = 0; kk < 16; kk++) {
            float4 a = *(const float4*)(&As[kk][0] + ty * 4);
            float4 b = *(const float4*)(&Bs[kk][0] + tx * 4);
            float ar[4] = {a.x, a.y, a.z, a.w};
            float br[4] = {b.x, b.y, b.z, b.w};
            #pragma unroll
            for (int i = 0; i < 4; i++)
                #pragma unroll
                for (int j = 0; j < 4; j++)
                    acc[i][j] = fmaf(ar[i], br[j], acc[i][j]);
        }
        __syncthreads();
    }

    int crow = blockIdx.y * 64 + ty * 4;
    int ccol = blockIdx.x * 64 + tx * 4;
    #pragma unroll
    for (int i = 0; i < 4; i++) {
        float4 o;
        o.x = acc[i][0] * alpha; o.y = acc[i][1] * alpha;
        o.z = acc[i][2] * alpha; o.w = acc[i][3] * alpha;
        *(float4*)(&C[(long long)(crow + i) * N + ccol]) = o;
    }
}

// ---------------- RMSNorm + RoPE for Q (also leaves gate in g_qraw for later) ----------------
__global__ void qnorm_rope(const float* __restrict__ qraw, const float* __restrict__ cosb,
                           const float* __restrict__ sinb, const float* __restrict__ w,
                           float* __restrict__ q)
{
    int s = blockIdx.x, h = blockIdx.y, b = blockIdx.z;
    int d = threadIdx.x;                       // 128
    long long bs = (long long)b * S_ + s;
    float x = qraw[bs * 4096 + h * 256 + d];   // first HD of the 2*HD head block
    float t = x * x;
    #pragma unroll
    for (int o = 16; o; o >>= 1) t += __shfl_xor_sync(0xffffffffu, t, o);
    __shared__ float ws[4];
    if ((d & 31) == 0) ws[d >> 5] = t;
    __syncthreads();
    float var = (ws[0] + ws[1] + ws[2] + ws[3]) * (1.0f / 128.0f);
    float xn = x * rsqrtf(var + 1e-6f) * w[d];
    __shared__ float sh[128];
    sh[d] = xn;
    __syncthreads();
    float other = (d < 64) ? -sh[d + 64] : sh[d - 64];
    float c = cosb[bs * 128 + d], sn = sinb[bs * 128 + d];
    q[(((long long)b * NH_ + h) * S_ + s) * HD_ + d] = xn * c + other * sn;
}

__global__ void knorm_rope(const float* __restrict__ kraw, const float* __restrict__ cosb,
                           const float* __restrict__ sinb, const float* __restrict__ w,
                           float* __restrict__ k)
{
    int s = blockIdx.x, h = blockIdx.y, b = blockIdx.z;
    int d = threadIdx.x;
    long long bs = (long long)b * S_ + s;
    float x = kraw[bs * 1024 + h * 128 + d];
    float t = x * x;
    #pragma unroll
    for (int o = 16; o; o >>= 1) t += __shfl_xor_sync(0xffffffffu, t, o);
    __shared__ float ws[4];
    if ((d & 31) == 0) ws[d >> 5] = t;
    __syncthreads();
    float var = (ws[0] + ws[1] + ws[2] + ws[3]) * (1.0f / 128.0f);
    float xn = x * rsqrtf(var + 1e-6f) * w[d];
    __shared__ float sh[128];
    sh[d] = xn;
    __syncthreads();
    float other = (d < 64) ? -sh[d + 64] : sh[d - 64];
    float c = cosb[bs * 128 + d], sn = sinb[bs * 128 + d];
    k[(((long long)b * NKV_ + h) * S_ + s) * HD_ + d] = xn * c + other * sn;
}

// ---------------- V transpose: [bs, kvh*128+d] -> [b,kvh,d,s] ----------------
__global__ void vtrans_kernel(const float* __restrict__ vraw, float* __restrict__ vt)
{
    __shared__ float tile[32][33];
    int z = blockIdx.z; int b = z >> 3; int kvh = z & 7;
    int s0 = blockIdx.x * 32;
    int d0 = blockIdx.y * 32;
    int tx = threadIdx.x;   // 32
    int ty = threadIdx.y;   // 8
    for (int r = ty; r < 32; r += 8)
        tile[r][tx] = vraw[((size_t)(b * S_ + s0 + r)) * 1024 + kvh * 128 + d0 + tx];
    __syncthreads();
    for (int r = ty; r < 32; r += 8)
        vt[((size_t)z * 128 + d0 + r) * 2048 + s0 + tx] = tile[tx][r];
}

// ---------------- Row softmax with "min-20" masked fill, in-place on attn ----------------
__global__ __launch_bounds__(256) void softmax_kernel(float* __restrict__ attn)
{
    int qi = blockIdx.x;
    int z  = blockIdx.y;            // b*NH + h
    float* row = attn + ((size_t)z * S_ + qi) * S_;
    int tid = threadIdx.x;          // 256
    __shared__ float p[2048];
    float mn = 3.4e38f, mx = -3.4e38f;
    for (int c = tid; c < S_; c += 256) {
        float v = row[c];
        p[c] = v;
        mn = fminf(mn, v);
        if (c <= qi) mx = fmaxf(mx, v);
    }
    #pragma unroll
    for (int o = 16; o; o >>= 1) {
        mn = fminf(mn, __shfl_xor_sync(0xffffffffu, mn, o));
        mx = fmaxf(mx, __shfl_xor_sync(0xffffffffu, mx, o));
    }
    __shared__ float smn[8], smx[8], ssum[8];
    if ((tid & 31) == 0) { smn[tid >> 5] = mn; smx[tid >> 5] = mx; }
    __syncthreads();
    mn = smn[0]; mx = smx[0];
    #pragma unroll
    for (int i = 1; i < 8; i++) { mn = fminf(mn, smn[i]); mx = fmaxf(mx, smx[i]); }
    float mval = mn - 20.f;             // amin(row) - 20 fills masked (k>qi) entries
    float M = fmaxf(mx, mval);
    float sum = 0.f;
    for (int c = tid; c < S_; c += 256) {
        float v = (c <= qi) ? p[c] : mval;
        float e = __expf(v - M);
        p[c] = e;
        sum += e;
    }
    #pragma unroll
    for (int o = 16; o; o >>= 1) sum += __shfl_xor_sync(0xffffffffu, sum, o);
    if ((tid & 31) == 0) ssum[tid >> 5] = sum;
    __syncthreads();
    sum = ssum[0];
    #pragma unroll
    for (int i = 1; i < 8; i++) sum += ssum[i];
    float inv = 1.f / sum;
    for (int c = tid; c < S_; c += 256)
        row[c] = p[c] * inv;
}

// ---------------- gate: av[bs, h*128+d] = avp[b,h,s,d] * sigmoid(gate) ----------------
__global__ void gate_kernel(const float* __restrict__ avp, const float* __restrict__ qraw,
                            float* __restrict__ av)
{
    size_t i = (size_t)blockIdx.x * blockDim.x + threadIdx.x;
    if (i >= (size_t)BS_ * 2048) return;
    int d = (int)(i & 127);
    int h = (int)((i >> 7) & 15);
    int s = (int)((i >> 11) & 2047);
    int b = (int)(i >> 22);
    float val = avp[(((size_t)(b * NH_ + h) * S_ + s) << 7) + d];
    float g   = qraw[(((size_t)(b * S_ + s)) << 12) + h * 256 + 128 + d];
    float sig = 1.f / (1.f + __expf(-g));
    av[(((size_t)(b * S_ + s)) << 11) + h * 128 + d] = val * sig;
}

// ---------------- launch ----------------
extern "C" void kernel_launch(void* const* d_in, const int* in_sizes, int n_in,
                              void* d_out, int out_size)
{
    const float* hidden = (const float*)d_in[0];
    const float* cosb   = (const float*)d_in[1];
    const float* sinb   = (const float*)d_in[2];
    // d_in[3] attention_mask: causal triu(k=1) — applied analytically (k>q)
    const float* Wq = (const float*)d_in[4];
    const float* Wk = (const float*)d_in[5];
    const float* Wv = (const float*)d_in[6];
    const float* Wo = (const float*)d_in[7];
    const float* qw = (const float*)d_in[8];
    const float* kw = (const float*)d_in[9];

    float* out  = (float*)d_out;                         // [B,S,H]
    float* attn = out + (size_t)B_ * S_ * H_;            // [B,NH,S,S]

    float *qraw, *kraw, *vraw, *q, *k, *vt, *avp, *av;
    cudaGetSymbolAddress((void**)&qraw, g_qraw);
    cudaGetSymbolAddress((void**)&kraw, g_kraw);
    cudaGetSymbolAddress((void**)&vraw, g_vraw);
    cudaGetSymbolAddress((void**)&q,    g_q);
    cudaGetSymbolAddress((void**)&k,    g_k);
    cudaGetSymbolAddress((void**)&vt,   g_vt);
    cudaGetSymbolAddress((void**)&avp,  g_avp);
    cudaGetSymbolAddress((void**)&av,   g_av);

    // 1) QKV projections (NT GEMMs)
    gemm_nt<<<dim3(64, 64, 1), 256>>>(hidden, Wq, qraw, 4096, 4096, 2048, 0, 0, 0, 1.f, 0);
    gemm_nt<<<dim3(16, 64, 1), 256>>>(hidden, Wk, kraw, 4096, 1024, 2048, 0, 0, 0, 1.f, 0);
    gemm_nt<<<dim3(16, 64, 1), 256>>>(hidden, Wv, vraw, 4096, 1024, 2048, 0, 0, 0, 1.f, 0);

    // 2) norms + rope + layout transforms
    qnorm_rope<<<dim3(S_, NH_, B_), 128>>>(qraw, cosb, sinb, qw, q);
    knorm_rope<<<dim3(S_, NKV_, B_), 128>>>(kraw, cosb, sinb, kw, k);
    vtrans_kernel<<<dim3(64, 4, 16), dim3(32, 8)>>>(vraw, vt);

    // 3) scores = scale * Q K^T  -> directly into attn output region
    gemm_nt<<<dim3(32, 32, 32), 256>>>(q, k, attn, 2048, 2048, 128,
                                       (long long)S_ * HD_, (long long)S_ * HD_,
                                       (long long)S_ * S_, SCALE_, 1);

    // 4) masked softmax in-place on attn
    softmax_kernel<<<dim3(S_, B_ * NH_), 256>>>(attn);

    // 5) P @ V (GEMM against transposed V for reuse)
    gemm_nt<<<dim3(2, 32, 32), 256>>>(attn, vt, avp, 2048, 128, 2048,
                                      (long long)S_ * S_, (long long)HD_ * S_,
                                      (long long)S_ * HD_, 1.f, 1);

    // 6) gating epilogue
    gate_kernel<<<(unsigned)(((size_t)BS_ * 2048 + 255) / 256), 256>>>(avp, qraw, av);

    // 7) output projection
    gemm_nt<<<dim3(32, 64, 1), 256>>>(av, Wo, out, 4096, 2048, 2048, 0, 0, 0, 1.f, 0);
}

// round 2
// speedup vs baseline: 2.8343x; 2.8343x over previous
#include <cuda_runtime.h>
#include <cstdint>
#include <cstddef>

#define B_  2
#define S_  2048
#define H_  2048
#define NH_ 16
#define NKV_ 8
#define HD_ 128
#define BS_ 4096
#define SCALE_ 0.08838834764831845f

// ---------------- scratch ----------------
__device__ float g_qraw[(size_t)BS_ * (2 * NH_ * HD_)];
__device__ float g_kraw[(size_t)BS_ * (NKV_ * HD_)];
__device__ float g_vraw[(size_t)BS_ * (NKV_ * HD_)];
__device__ float g_q  [(size_t)B_ * NH_  * S_ * HD_];
__device__ float g_k  [(size_t)B_ * NKV_ * S_ * HD_];
__device__ float g_vt [(size_t)B_ * NKV_ * HD_ * S_];
__device__ float g_avp[(size_t)B_ * NH_  * S_ * HD_];
__device__ float g_av [(size_t)BS_ * (NH_ * HD_)];

__device__ __forceinline__ unsigned f2tf(float x) {
    unsigned r;
    asm("cvt.rna.tf32.f32 %0, %1;" : "=r"(r) : "f"(x));
    return r;
}

// ---------------- TF32 tensor-core GEMM: C = alpha * A(MxK) * B(NxK)^T ----------------
// Block tile 128x128, K-tile 32, 256 threads (8 warps, each 64x32).
// Requires M%128==0, N%128==0, K%32==0 (true for all call sites).
#define SMEM_FLOATS (2 * 128 * 36)
__global__ __launch_bounds__(256) void gemm_tf32(
    const float* __restrict__ A, const float* __restrict__ Bm, float* __restrict__ C,
    int M, int N, int K,
    long long sA, long long sB, long long sC,
    float alpha, int gqaB)
{
    int z = blockIdx.z;
    long long offB;
    if (gqaB) { int b = z >> 4; int h = z & 15; offB = ((long long)b * NKV_ + (h >> 1)) * sB; }
    else        offB = (long long)z * sB;
    A  += (long long)z * sA;
    Bm += offB;
    C  += (long long)z * sC;

    extern __shared__ float smem[];
    float (*As)[128][36] = (float(*)[128][36])smem;
    float (*Bs)[128][36] = (float(*)[128][36])(smem + SMEM_FLOATS);

    const int tid  = threadIdx.x;
    const int lane = tid & 31;
    const int wid  = tid >> 5;
    const int g    = lane >> 2;      // group id 0..7
    const int tig  = lane & 3;       // thread-in-group 0..3
    const int warpM = (wid >> 2) * 64;   // 0 or 64
    const int warpN = (wid & 3) * 32;    // 0,32,64,96

    // global->smem staging mapping: 128 rows x 32 cols, float4 per thread x4
    const int ldr = tid >> 3;        // 0..31 (row within 32-row slab)
    const int ldc = (tid & 7) * 4;   // 0..28 step 4

    const float* Ap = A  + (long long)(blockIdx.y * 128 + ldr) * K + ldc;
    const float* Bp = Bm + (long long)(blockIdx.x * 128 + ldr) * K + ldc;
    const long long rowStep = (long long)32 * K;

    float acc[4][4][4] = {};

    // ---- prologue: tile 0 into buffer 0 ----
    {
        float4 ra[4], rb[4];
        #pragma unroll
        for (int p = 0; p < 4; p++) {
            ra[p] = *(const float4*)(Ap + p * rowStep);
            rb[p] = *(const float4*)(Bp + p * rowStep);
        }
        #pragma unroll
        for (int p = 0; p < 4; p++) {
            float* a = &As[0][ldr + p * 32][ldc];
            a[0] = __uint_as_float(f2tf(ra[p].x)); a[1] = __uint_as_float(f2tf(ra[p].y));
            a[2] = __uint_as_float(f2tf(ra[p].z)); a[3] = __uint_as_float(f2tf(ra[p].w));
            float* b = &Bs[0][ldr + p * 32][ldc];
            b[0] = __uint_as_float(f2tf(rb[p].x)); b[1] = __uint_as_float(f2tf(rb[p].y));
            b[2] = __uint_as_float(f2tf(rb[p].z)); b[3] = __uint_as_float(f2tf(rb[p].w));
        }
    }
    __syncthreads();

    const int nK = K >> 5;
    int buf = 0;
    for (int kt = 0; kt < nK; kt++) {
        const bool has_next = (kt + 1 < nK);
        float4 ra[4], rb[4];
        if (has_next) {
            const int k0 = (kt + 1) << 5;
            #pragma unroll
            for (int p = 0; p < 4; p++) {
                ra[p] = *(const float4*)(Ap + p * rowStep + k0);
                rb[p] = *(const float4*)(Bp + p * rowStep + k0);
            }
        }

        const float (*Ab)[36] = As[buf];
        const float (*Bb)[36] = Bs[buf];
        #pragma unroll
        for (int kc = 0; kc < 32; kc += 8) {
            unsigned a[4][4], b[4][2];
            #pragma unroll
            for (int i = 0; i < 4; i++) {
                const int r0 = warpM + i * 16 + g;
                a[i][0] = __float_as_uint(Ab[r0    ][kc + tig    ]);
                a[i][1] = __float_as_uint(Ab[r0 + 8][kc + tig    ]);
                a[i][2] = __float_as_uint(Ab[r0    ][kc + tig + 4]);
                a[i][3] = __float_as_uint(Ab[r0 + 8][kc + tig + 4]);
            }
            #pragma unroll
            for (int j = 0; j < 4; j++) {
                const int rn = warpN + j * 8 + g;
                b[j][0] = __float_as_uint(Bb[rn][kc + tig    ]);
                b[j][1] = __float_as_uint(Bb[rn][kc + tig + 4]);
            }
            #pragma unroll
            for (int i = 0; i < 4; i++)
                #pragma unroll
                for (int j = 0; j < 4; j++) {
                    asm volatile(
                        "mma.sync.aligned.m16n8k8.row.col.f32.tf32.tf32.f32 "
                        "{%0,%1,%2,%3}, {%4,%5,%6,%7}, {%8,%9}, {%0,%1,%2,%3};"
                        : "+f"(acc[i][j][0]), "+f"(acc[i][j][1]),
                          "+f"(acc[i][j][2]), "+f"(acc[i][j][3])
                        : "r"(a[i][0]), "r"(a[i][1]), "r"(a[i][2]), "r"(a[i][3]),
                          "r"(b[j][0]), "r"(b[j][1]));
                }
        }

        if (has_next) {
            const int nb = buf ^ 1;
            #pragma unroll
            for (int p = 0; p < 4; p++) {
                float* a = &As[nb][ldr + p * 32][ldc];
                a[0] = __uint_as_float(f2tf(ra[p].x)); a[1] = __uint_as_float(f2tf(ra[p].y));
                a[2] = __uint_as_float(f2tf(ra[p].z)); a[3] = __uint_as_float(f2tf(ra[p].w));
                float* b = &Bs[nb][ldr + p * 32][ldc];
                b[0] = __uint_as_float(f2tf(rb[p].x)); b[1] = __uint_as_float(f2tf(rb[p].y));
                b[2] = __uint_as_float(f2tf(rb[p].z)); b[3] = __uint_as_float(f2tf(rb[p].w));
            }
        }
        __syncthreads();
        buf ^= 1;
    }

    // ---- epilogue ----
    #pragma unroll
    for (int i = 0; i < 4; i++) {
        const int r0 = blockIdx.y * 128 + warpM + i * 16 + g;
        #pragma unroll
        for (int j = 0; j < 4; j++) {
            const int c0 = blockIdx.x * 128 + warpN + j * 8 + 2 * tig;
            float2 v0 = { acc[i][j][0] * alpha, acc[i][j][1] * alpha };
            float2 v1 = { acc[i][j][2] * alpha, acc[i][j][3] * alpha };
            *(float2*)(&C[(long long)r0 * N + c0])       = v0;
            *(float2*)(&C[(long long)(r0 + 8) * N + c0]) = v1;
        }
    }
}

// ---------------- RMSNorm + RoPE for Q ----------------
__global__ void qnorm_rope(const float* __restrict__ qraw, const float* __restrict__ cosb,
                           const float* __restrict__ sinb, const float* __restrict__ w,
                           float* __restrict__ q)
{
    int s = blockIdx.x, h = blockIdx.y, b = blockIdx.z;
    int d = threadIdx.x;
    long long bs = (long long)b * S_ + s;
    float x = qraw[bs * 4096 + h * 256 + d];
    float t = x * x;
    #pragma unroll
    for (int o = 16; o; o >>= 1) t += __shfl_xor_sync(0xffffffffu, t, o);
    __shared__ float ws[4];
    if ((d & 31) == 0) ws[d >> 5] = t;
    __syncthreads();
    float var = (ws[0] + ws[1] + ws[2] + ws[3]) * (1.0f / 128.0f);
    float xn = x * rsqrtf(var + 1e-6f) * w[d];
    __shared__ float sh[128];
    sh[d] = xn;
    __syncthreads();
    float other = (d < 64) ? -sh[d + 64] : sh[d - 64];
    float c = cosb[bs * 128 + d], sn = sinb[bs * 128 + d];
    q[(((long long)b * NH_ + h) * S_ + s) * HD_ + d] = xn * c + other * sn;
}

__global__ void knorm_rope(const float* __restrict__ kraw, const float* __restrict__ cosb,
                           const float* __restrict__ sinb, const float* __restrict__ w,
                           float* __restrict__ k)
{
    int s = blockIdx.x, h = blockIdx.y, b = blockIdx.z;
    int d = threadIdx.x;
    long long bs = (long long)b * S_ + s;
    float x = kraw[bs * 1024 + h * 128 + d];
    float t = x * x;
    #pragma unroll
    for (int o = 16; o; o >>= 1) t += __shfl_xor_sync(0xffffffffu, t, o);
    __shared__ float ws[4];
    if ((d & 31) == 0) ws[d >> 5] = t;
    __syncthreads();
    float var = (ws[0] + ws[1] + ws[2] + ws[3]) * (1.0f / 128.0f);
    float xn = x * rsqrtf(var + 1e-6f) * w[d];
    __shared__ float sh[128];
    sh[d] = xn;
    __syncthreads();
    float other = (d < 64) ? -sh[d + 64] : sh[d - 64];
    float c = cosb[bs * 128 + d], sn = sinb[bs * 128 + d];
    k[(((long long)b * NKV_ + h) * S_ + s) * HD_ + d] = xn * c + other * sn;
}

// ---------------- V transpose ----------------
__global__ void vtrans_kernel(const float* __restrict__ vraw, float* __restrict__ vt)
{
    __shared__ float tile[32][33];
    int z = blockIdx.z; int b = z >> 3; int kvh = z & 7;
    int s0 = blockIdx.x * 32;
    int d0 = blockIdx.y * 32;
    int tx = threadIdx.x;
    int ty = threadIdx.y;
    for (int r = ty; r < 32; r += 8)
        tile[r][tx] = vraw[((size_t)(b * S_ + s0 + r)) * 1024 + kvh * 128 + d0 + tx];
    __syncthreads();
    for (int r = ty; r < 32; r += 8)
        vt[((size_t)z * 128 + d0 + r) * 2048 + s0 + tx] = tile[tx][r];
}

// ---------------- softmax with min-20 mask fill ----------------
__global__ __launch_bounds__(256) void softmax_kernel(float* __restrict__ attn)
{
    int qi = blockIdx.x;
    int z  = blockIdx.y;
    float* row = attn + ((size_t)z * S_ + qi) * S_;
    int tid = threadIdx.x;
    __shared__ float p[2048];
    float mn = 3.4e38f, mx = -3.4e38f;
    for (int c = tid; c < S_; c += 256) {
        float v = row[c];
        p[c] = v;
        mn = fminf(mn, v);
        if (c <= qi) mx = fmaxf(mx, v);
    }
    #pragma unroll
    for (int o = 16; o; o >>= 1) {
        mn = fminf(mn, __shfl_xor_sync(0xffffffffu, mn, o));
        mx = fmaxf(mx, __shfl_xor_sync(0xffffffffu, mx, o));
    }
    __shared__ float smn[8], smx[8], ssum[8];
    if ((tid & 31) == 0) { smn[tid >> 5] = mn; smx[tid >> 5] = mx; }
    __syncthreads();
    mn = smn[0]; mx = smx[0];
    #pragma unroll
    for (int i = 1; i < 8; i++) { mn = fminf(mn, smn[i]); mx = fmaxf(mx, smx[i]); }
    float mval = mn - 20.f;
    float M = fmaxf(mx, mval);
    float sum = 0.f;
    for (int c = tid; c < S_; c += 256) {
        float v = (c <= qi) ? p[c] : mval;
        float e = __expf(v - M);
        p[c] = e;
        sum += e;
    }
    #pragma unroll
    for (int o = 16; o; o >>= 1) sum += __shfl_xor_sync(0xffffffffu, sum, o);
    if ((tid & 31) == 0) ssum[tid >> 5] = sum;
    __syncthreads();
    sum = ssum[0];
    #pragma unroll
    for (int i = 1; i < 8; i++) sum += ssum[i];
    float inv = 1.f / sum;
    for (int c = tid; c < S_; c += 256)
        row[c] = p[c] * inv;
}

// ---------------- gate ----------------
__global__ void gate_kernel(const float* __restrict__ avp, const float* __restrict__ qraw,
                            float* __restrict__ av)
{
    size_t i = (size_t)blockIdx.x * blockDim.x + threadIdx.x;
    if (i >= (size_t)BS_ * 2048) return;
    int d = (int)(i & 127);
    int h = (int)((i >> 7) & 15);
    int s = (int)((i >> 11) & 2047);
    int b = (int)(i >> 22);
    float val = avp[(((size_t)(b * NH_ + h) * S_ + s) << 7) + d];
    float g   = qraw[(((size_t)(b * S_ + s)) << 12) + h * 256 + 128 + d];
    float sig = 1.f / (1.f + __expf(-g));
    av[(((size_t)(b * S_ + s)) << 11) + h * 128 + d] = val * sig;
}

// ---------------- launch ----------------
extern "C" void kernel_launch(void* const* d_in, const int* in_sizes, int n_in,
                              void* d_out, int out_size)
{
    const float* hidden = (const float*)d_in[0];
    const float* cosb   = (const float*)d_in[1];
    const float* sinb   = (const float*)d_in[2];
    const float* Wq = (const float*)d_in[4];
    const float* Wk = (const float*)d_in[5];
    const float* Wv = (const float*)d_in[6];
    const float* Wo = (const float*)d_in[7];
    const float* qw = (const float*)d_in[8];
    const float* kw = (const float*)d_in[9];

    float* out  = (float*)d_out;
    float* attn = out + (size_t)B_ * S_ * H_;

    float *qraw, *kraw, *vraw, *q, *k, *vt, *avp, *av;
    cudaGetSymbolAddress((void**)&qraw, g_qraw);
    cudaGetSymbolAddress((void**)&kraw, g_kraw);
    cudaGetSymbolAddress((void**)&vraw, g_vraw);
    cudaGetSymbolAddress((void**)&q,    g_q);
    cudaGetSymbolAddress((void**)&k,    g_k);
    cudaGetSymbolAddress((void**)&vt,   g_vt);
    cudaGetSymbolAddress((void**)&avp,  g_avp);
    cudaGetSymbolAddress((void**)&av,   g_av);

    const int SMEM_BYTES = 2 * SMEM_FLOATS * 4;  // 73728
    cudaFuncSetAttribute(gemm_tf32, cudaFuncAttributeMaxDynamicSharedMemorySize, SMEM_BYTES);

    // 1) QKV projections
    gemm_tf32<<<dim3(32, 32, 1), 256, SMEM_BYTES>>>(hidden, Wq, qraw, 4096, 4096, 2048, 0, 0, 0, 1.f, 0);
    gemm_tf32<<<dim3(8,  32, 1), 256, SMEM_BYTES>>>(hidden, Wk, kraw, 4096, 1024, 2048, 0, 0, 0, 1.f, 0);
    gemm_tf32<<<dim3(8,  32, 1), 256, SMEM_BYTES>>>(hidden, Wv, vraw, 4096, 1024, 2048, 0, 0, 0, 1.f, 0);

    // 2) norms + rope + layout
    qnorm_rope<<<dim3(S_, NH_, B_), 128>>>(qraw, cosb, sinb, qw, q);
    knorm_rope<<<dim3(S_, NKV_, B_), 128>>>(kraw, cosb, sinb, kw, k);
    vtrans_kernel<<<dim3(64, 4, 16), dim3(32, 8)>>>(vraw, vt);

    // 3) scores
    gemm_tf32<<<dim3(16, 16, 32), 256, SMEM_BYTES>>>(q, k, attn, 2048, 2048, 128,
                                       (long long)S_ * HD_, (long long)S_ * HD_,
                                       (long long)S_ * S_, SCALE_, 1);

    // 4) softmax
    softmax_kernel<<<dim3(S_, B_ * NH_), 256>>>(attn);

    // 5) P @ V
    gemm_tf32<<<dim3(1, 16, 32), 256, SMEM_BYTES>>>(attn, vt, avp, 2048, 128, 2048,
                                      (long long)S_ * S_, (long long)HD_ * S_,
                                      (long long)S_ * HD_, 1.f, 1);

    // 6) gate
    gate_kernel<<<(unsigned)(((size_t)BS_ * 2048 + 255) / 256), 256>>>(avp, qraw, av);

    // 7) output projection
    gemm_tf32<<<dim3(16, 32, 1), 256, SMEM_BYTES>>>(av, Wo, out, 4096, 2048, 2048, 0, 0, 0, 1.f, 0);
}